// round 15
// baseline (speedup 1.0000x reference)
#include <cuda_runtime.h>
#include <cuda_bf16.h>

// CompositeValueNoise, spatially-binned v13.
// vs R14 (best, 94.0us): main kernel's lerp tree converted to packed
// fma.rn.f32x2 (SASS FFMA2; PTX-only pattern). lerp(a,b,w) restructured as
// fma(w, b, fma(-w, a, a)) so every level is 28 FFMA2 instead of 56 scalar
// FADD/FFMA. Corners loaded as ulonglong2 (no pack cost). Pipeline unchanged.

#define N_FIELDS 4
#define MAXN 2000000
#define BBITS 6
#define BDIM (1 << BBITS)            // 64
#define NBUCK (BDIM * BDIM * BDIM)   // 262144
#define SCAN_BLKS (NBUCK / 1024)     // 256

typedef unsigned long long ull;

__device__ int    g_hist[NBUCK];     // zero at load; re-zeroed by main kernel
__device__ int    g_counter;
__device__ float4 g_sorted[MAXN];

__device__ __forceinline__ int cell_key(float px, float py, float pz) {
    int ci = min(max((int)(px * (float)BDIM), 0), BDIM - 1);
    int cj = min(max((int)(py * (float)BDIM), 0), BDIM - 1);
    int ck = min(max((int)(pz * (float)BDIM), 0), BDIM - 1);
    return (ci << (2 * BBITS)) | (cj << BBITS) | ck;   // k innermost
}

__global__ void hist_kernel(const float* __restrict__ x, int n) {
    int t = blockIdx.x * blockDim.x + threadIdx.x;
    int p0 = t * 4;
    if (p0 >= n) return;
    if (p0 + 4 <= n) {
        const float4* xv = reinterpret_cast<const float4*>(x) + 3 * (size_t)t;
        float4 a = __ldcs(xv + 0), b = __ldcs(xv + 1), c = __ldcs(xv + 2);
        atomicAdd(&g_hist[cell_key(a.x, a.y, a.z)], 1);
        atomicAdd(&g_hist[cell_key(a.w, b.x, b.y)], 1);
        atomicAdd(&g_hist[cell_key(b.z, b.w, c.x)], 1);
        atomicAdd(&g_hist[cell_key(c.y, c.z, c.w)], 1);
    } else {
        for (int p = p0; p < n; ++p)
            atomicAdd(&g_hist[cell_key(x[3*p], x[3*p+1], x[3*p+2])], 1);
    }
}

// Coalesced block scan of 1024 ints; block takes its global segment base via
// one early atomicAdd on g_counter, folded into the stored prefixes, so
// g_hist ends holding ABSOLUTE exclusive bucket bases. Segment order is
// run-arbitrary; each point's slot and value are unchanged -> deterministic.
__global__ void scan1_kernel() {
    __shared__ int warp_sums[8];
    __shared__ int s_base;
    int b = blockIdx.x, t = threadIdx.x;
    int lane = t & 31, wid = t >> 5;
    int base = b * 1024 + t * 4;

    int4 v = *reinterpret_cast<int4*>(&g_hist[base]);
    int tot = v.x + v.y + v.z + v.w;

    int inc = tot;
    #pragma unroll
    for (int o = 1; o < 32; o <<= 1) {
        int u = __shfl_up_sync(0xffffffffu, inc, o);
        if (lane >= o) inc += u;
    }
    if (lane == 31) warp_sums[wid] = inc;
    __syncthreads();
    if (wid == 0 && lane < 8) {
        int w = warp_sums[lane];
        #pragma unroll
        for (int o = 1; o < 8; o <<= 1) {
            int u = __shfl_up_sync(0xffu, w, o);
            if (lane >= o) w += u;
        }
        warp_sums[lane] = w;
        if (lane == 7) s_base = atomicAdd(&g_counter, w);  // w == block total
    }
    __syncthreads();
    int excl = s_base + (wid ? warp_sums[wid - 1] : 0) + inc - tot;

    int4 r;
    r.x = excl;
    r.y = excl + v.x;
    r.z = excl + v.x + v.y;
    r.w = excl + v.x + v.y + v.z;
    *reinterpret_cast<int4*>(&g_hist[base]) = r;
}

__device__ __forceinline__ void scatter_one(float px, float py, float pz, int i) {
    int pos = atomicAdd(&g_hist[cell_key(px, py, pz)], 1);
    __stcg(&g_sorted[pos], make_float4(px, py, pz, __int_as_float(i)));
}

__global__ void scatter_kernel(const float* __restrict__ x, int n) {
    int t = blockIdx.x * blockDim.x + threadIdx.x;
    int p0 = t * 4;
    if (p0 >= n) return;
    if (p0 + 4 <= n) {
        const float4* xv = reinterpret_cast<const float4*>(x) + 3 * (size_t)t;
        float4 a = __ldcs(xv + 0), b = __ldcs(xv + 1), c = __ldcs(xv + 2);
        scatter_one(a.x, a.y, a.z, p0 + 0);
        scatter_one(a.w, b.x, b.y, p0 + 1);
        scatter_one(b.z, b.w, c.x, p0 + 2);
        scatter_one(c.y, c.z, c.w, p0 + 3);
    } else {
        for (int p = p0; p < n; ++p)
            scatter_one(x[3*p], x[3*p+1], x[3*p+2], p);
    }
}

// ---- packed f32x2 helpers ----

#define FMA2(d, a, b, c) \
    asm("fma.rn.f32x2 %0, %1, %2, %3;" : "=l"(d) : "l"(a), "l"(b), "l"(c))

__device__ __forceinline__ ull pack2(float lo, float hi) {
    ull r;
    asm("mov.b64 %0, {%1, %2};" : "=l"(r) : "f"(lo), "f"(hi));
    return r;
}

struct P4 { ull lo, hi; };   // packed float4: (x,y) and (z,w)

// r = a*(1-w) + b*w  computed as fma(w, b, fma(-w, a, a)); w2/nw2 = (w,w),(-w,-w)
__device__ __forceinline__ P4 lerpP(P4 a, P4 b, ull w2, ull nw2) {
    P4 r; ull tlo, thi;
    FMA2(tlo, nw2, a.lo, a.lo);
    FMA2(r.lo, w2, b.lo, tlo);
    FMA2(thi, nw2, a.hi, a.hi);
    FMA2(r.hi, w2, b.hi, thi);
    return r;
}

__device__ __forceinline__ P4 ldP(const float* __restrict__ p) {
    ulonglong2 v = __ldg(reinterpret_cast<const ulonglong2*>(p));
    P4 r; r.lo = v.x; r.hi = v.y;
    return r;
}

struct Lv {
    const float* base;
    int s0, s1;
    ull wx2, nwx2, wy2, nwy2, wz2, nwz2;
};

__device__ __forceinline__ Lv prep(const float* __restrict__ V, int res,
                                   float px, float py, float pz) {
    const float resf = (float)res;
    float xs = px * resf, ys = py * resf, zs = pz * resf;
    // x in [0,1) and xs >= 0: trunc == floor.
    int i0 = (int)xs, j0 = (int)ys, k0 = (int)zs;
    float tx = xs - (float)i0, ty = ys - (float)j0, tz = zs - (float)k0;
    float wx = (3.0f - 2.0f * tx) * tx * tx;
    float wy = (3.0f - 2.0f * ty) * ty * ty;
    float wz = (3.0f - 2.0f * tz) * tz * tz;
    Lv L;
    L.wx2 = pack2(wx, wx);  L.nwx2 = pack2(-wx, -wx);
    L.wy2 = pack2(wy, wy);  L.nwy2 = pack2(-wy, -wy);
    L.wz2 = pack2(wz, wz);  L.nwz2 = pack2(-wz, -wz);
    const int r1 = res + 1;
    L.s1 = r1 * N_FIELDS;
    L.s0 = r1 * L.s1;
    L.base = V + (size_t)i0 * L.s0 + (size_t)j0 * L.s1 + (size_t)k0 * N_FIELDS;
    return L;
}

__device__ __forceinline__ void do_loads8(const Lv& L, P4 v[8]) {
    v[0] = ldP(L.base);
    v[1] = ldP(L.base + N_FIELDS);
    v[2] = ldP(L.base + L.s1);
    v[3] = ldP(L.base + L.s1 + N_FIELDS);
    v[4] = ldP(L.base + L.s0);
    v[5] = ldP(L.base + L.s0 + N_FIELDS);
    v[6] = ldP(L.base + L.s0 + L.s1);
    v[7] = ldP(L.base + L.s0 + L.s1 + N_FIELDS);
}

__device__ __forceinline__ P4 interp8(const Lv& L, const P4 v[8]) {
    // reference order: dim0 (wx), dim1 (wy), dim2 (wz)
    P4 a00 = lerpP(v[0], v[4], L.wx2, L.nwx2);
    P4 a01 = lerpP(v[1], v[5], L.wx2, L.nwx2);
    P4 a10 = lerpP(v[2], v[6], L.wx2, L.nwx2);
    P4 a11 = lerpP(v[3], v[7], L.wx2, L.nwx2);
    P4 b0 = lerpP(a00, a10, L.wy2, L.nwy2);
    P4 b1 = lerpP(a01, a11, L.wy2, L.nwy2);
    return lerpP(b0, b1, L.wz2, L.nwz2);
}

__global__ void __launch_bounds__(128, 12) composite_value_noise_kernel(
    const float* __restrict__ V16,
    const float* __restrict__ V32,
    const float* __restrict__ V64,
    const float* __restrict__ V128,
    float* __restrict__ out,
    int n)
{
    int p = blockIdx.x * blockDim.x + threadIdx.x;

    if (p < n) {
        float4 pt = __ldcs(&g_sorted[p]);
        const float px = pt.x, py = pt.y, pz = pt.z;
        const int   idx = __float_as_int(pt.w);

        // Pair 1: V16 + V32 — 16 loads issued before interpolation math.
        Lv l0 = prep(V16, 16, px, py, pz);
        Lv l1 = prep(V32, 32, px, py, pz);
        P4 va[8], vb[8];
        do_loads8(l0, va);
        do_loads8(l1, vb);
        P4 n0 = interp8(l0, va);
        P4 n1 = interp8(l1, vb);

        // Pair 2: V64 + V128.
        Lv l2 = prep(V64, 64, px, py, pz);
        Lv l3 = prep(V128, 128, px, py, pz);
        do_loads8(l2, va);
        do_loads8(l3, vb);
        P4 n2 = interp8(l2, va);
        P4 n3 = interp8(l3, vb);

        // acc = n0 + 0.5 n1 + 0.25 n2 + 0.125 n3 (reference order), packed.
        const ull c_half    = 0x3F0000003F000000ull;  // (0.5, 0.5)
        const ull c_quarter = 0x3E8000003E800000ull;  // (0.25, 0.25)
        const ull c_eighth  = 0x3E0000003E000000ull;  // (0.125, 0.125)
        ull acc_lo, acc_hi;
        FMA2(acc_lo, c_half, n1.lo, n0.lo);
        FMA2(acc_lo, c_quarter, n2.lo, acc_lo);
        FMA2(acc_lo, c_eighth, n3.lo, acc_lo);
        FMA2(acc_hi, c_half, n1.hi, n0.hi);
        FMA2(acc_hi, c_quarter, n2.hi, acc_hi);
        FMA2(acc_hi, c_eighth, n3.hi, acc_hi);

        ulonglong2 accv; accv.x = acc_lo; accv.y = acc_hi;
        __stcg(reinterpret_cast<ulonglong2*>(out) + idx, accv);
    }

    // Tail: restore the "g_hist is zero" invariant for the next invocation
    // (main kernel never reads g_hist, so this is safe within this launch).
    int z = blockIdx.x * blockDim.x + threadIdx.x;
    if (z < NBUCK / 4)
        __stcg(reinterpret_cast<int4*>(g_hist) + z, make_int4(0, 0, 0, 0));
    if (z == 0) g_counter = 0;
}

extern "C" void kernel_launch(void* const* d_in, const int* in_sizes, int n_in,
                              void* d_out, int out_size) {
    const float* x    = (const float*)d_in[0];
    const float* V16  = (const float*)d_in[1];
    const float* V32  = (const float*)d_in[2];
    const float* V64  = (const float*)d_in[3];
    const float* V128 = (const float*)d_in[4];
    float* out = (float*)d_out;

    int n = in_sizes[0] / 3;
    const int T = 256;
    int nquads = (n + 3) / 4;

    hist_kernel<<<(nquads + T - 1) / T, T>>>(x, n);
    scan1_kernel<<<SCAN_BLKS, 256>>>();
    scatter_kernel<<<(nquads + T - 1) / T, T>>>(x, n);

    const int TM = 128;
    int blocks = (n + TM - 1) / TM;
    composite_value_noise_kernel<<<blocks, TM>>>(V16, V32, V64, V128, out, n);
}